// round 14
// baseline (speedup 1.0000x reference)
#include <cuda_runtime.h>

#define BATCH 16384
#define CTX   10
#define MAXC  24
#define EMBED 128
#define WPB   2
#define THREADS (WPB * 32)               // 64
#define GRID  (BATCH / WPB)              // 8192
#define PITCH 36   // transpose pitch: STS banks (4l+i)%32 distinct; 144B rows, LDS.128 conflict-free

// Grid-reduction state (validated R11): zero-init at load; last block resets
// after publishing. Ordering via release/acquire atomics (L2) — no fences,
// no CCTL.IVALL, no allocation.
__device__ float        g_acc;
__device__ unsigned int g_count;

// Predicated 16B-per-lane async copy global->shared (LDGSTS, .cg = L1 bypass).
// Not issued when pred==0: the stale smem row is discarded later by select.
__device__ __forceinline__ void cp_async16_pred(unsigned int sdst, const void* gsrc,
                                                int pred) {
    asm volatile("{\n\t"
                 ".reg .pred p;\n\t"
                 "setp.ne.s32 p, %0, 0;\n\t"
                 "@p cp.async.cg.shared.global [%1], [%2], 16;\n\t"
                 "}"
                 :: "r"(pred), "r"(sdst), "l"(gsrc) : "memory");
}

__global__ __launch_bounds__(THREADS)
void cbow_hs_kernel(const int* __restrict__ context_words,
                    const int* __restrict__ paths,
                    const int* __restrict__ codes,
                    const int* __restrict__ mask,     // int32 0/1
                    const float* __restrict__ W_in,
                    const float* __restrict__ W_internal,
                    float* __restrict__ out)
{
    const int warp_id = threadIdx.x >> 5;
    const int lane    = threadIdx.x & 31;
    const int row     = blockIdx.x * WPB + warp_id;   // always < BATCH (8192*2)

    __shared__ float stage[WPB][MAXC][EMBED];     // 24.0 KB: staged node rows
    __shared__ float trans[WPB][MAXC * PITCH];    //  6.75 KB: partial-dot transpose
    __shared__ float warp_loss[WPB];

    float* st = &stage[warp_id][0][0];
    float* ws = trans[warp_id];

    // ---- RT1: all per-row scalars (warp-uniform idx vectors + per-lane tail).
    const int li  = (lane < MAXC) ? lane : (MAXC - 1);
    const int cj  = __ldg(codes + row * MAXC + li);
    const int mlj = __ldg(mask  + row * MAXC + li);
    const int4* p4 = reinterpret_cast<const int4*>(paths + row * MAXC);
    const int4* m4 = reinterpret_cast<const int4*>(mask  + row * MAXC);
    int4 P[6], M[6];
    #pragma unroll
    for (int q = 0; q < 6; q++) { P[q] = __ldg(p4 + q); M[q] = __ldg(m4 + q); }

    // ---- RT2a: ALL 24 node-row copies in flight via cp.async (no register
    // cost — this is what R10 couldn't afford). 512B per row, coalesced.
    const unsigned int sbase =
        (unsigned int)__cvta_generic_to_shared(st) + (unsigned int)(lane * 16);
    #pragma unroll
    for (int q = 0; q < 6; q++) {
        const int nodes[4] = {P[q].x, P[q].y, P[q].z, P[q].w};
        const int mks[4]   = {M[q].x, M[q].y, M[q].z, M[q].w};
        #pragma unroll
        for (int k = 0; k < 4; k++) {
            const int l = q * 4 + k;
            cp_async16_pred(sbase + (unsigned int)(l * EMBED * 4),
                            W_internal + (long)nodes[k] * EMBED + lane * 4,
                            mks[k]);
        }
    }
    asm volatile("cp.async.commit_group;" ::: "memory");

    // ---- RT2b: 10 context gathers (registers), overlapping the copies.
    const int* cw = context_words + row * CTX;
    float4 v = make_float4(0.f, 0.f, 0.f, 0.f);
    #pragma unroll
    for (int i = 0; i < CTX; i++) {
        const int w = __ldg(cw + i);
        const float4 e = __ldg(reinterpret_cast<const float4*>(
                                   W_in + (long)w * EMBED) + lane);
        v.x += e.x; v.y += e.y; v.z += e.z; v.w += e.w;
    }
    const float inv_ctx = 1.0f / (float)CTX;
    v.x *= inv_ctx; v.y *= inv_ctx; v.z *= inv_ctx; v.w *= inv_ctx;

    // ---- Drain copies, then partial dots from smem (contiguous 512B row
    // reads: conflict-free) into the transpose buffer.
    asm volatile("cp.async.wait_group 0;" ::: "memory");
    __syncwarp();

    #pragma unroll
    for (int l = 0; l < MAXC; l++) {
        const float4 e = *reinterpret_cast<const float4*>(st + l * EMBED + lane * 4);
        const float pt = fmaf(v.x, e.x,
                         fmaf(v.y, e.y,
                         fmaf(v.z, e.z, v.w * e.w)));
        ws[l * PITCH + lane] = pt;
    }
    __syncwarp();

    // ---- Tail: lane j (<24) sums step j's 32 partials via 8x LDS.128;
    // masked/garbage rows are discarded by the select (NaN-safe).
    float contrib = 0.0f;
    if (lane < MAXC) {
        const float4* rp = reinterpret_cast<const float4*>(ws + lane * PITCH);
        float4 a0 = rp[0], a1 = rp[1], a2 = rp[2], a3 = rp[3];
        const float4 b0 = rp[4], b1 = rp[5], b2 = rp[6], b3 = rp[7];
        a0.x += b0.x; a0.y += b0.y; a0.z += b0.z; a0.w += b0.w;
        a1.x += b1.x; a1.y += b1.y; a1.z += b1.z; a1.w += b1.w;
        a2.x += b2.x; a2.y += b2.y; a2.z += b2.z; a2.w += b2.w;
        a3.x += b3.x; a3.y += b3.y; a3.z += b3.z; a3.w += b3.w;
        float s = ((a0.x + a0.y) + (a0.z + a0.w))
                + ((a1.x + a1.y) + (a1.z + a1.w))
                + ((a2.x + a2.y) + (a2.z + a2.w))
                + ((a3.x + a3.y) + (a3.z + a3.w));

        const float sign = (float)(2 * cj - 1);
        const float x = -sign * s;
        const float sp = fmaxf(x, 0.0f) + __logf(1.0f + __expf(-fabsf(x)));
        contrib = mlj ? sp : 0.0f;
    }

    // ---- Warp + block reduce.
    contrib += __shfl_xor_sync(0xffffffffu, contrib, 16);
    contrib += __shfl_xor_sync(0xffffffffu, contrib, 8);
    contrib += __shfl_xor_sync(0xffffffffu, contrib, 4);
    contrib += __shfl_xor_sync(0xffffffffu, contrib, 2);
    contrib += __shfl_xor_sync(0xffffffffu, contrib, 1);
    if (lane == 0) warp_loss[warp_id] = contrib;
    __syncthreads();

    // ---- Fence-free grid finish (validated R11).
    if (threadIdx.x == 0) {
        const float s = warp_loss[0] + warp_loss[1];
        atomicAdd(&g_acc, s);

        unsigned int prev;
        asm volatile("atom.release.gpu.add.u32 %0, [%1], 1;"
                     : "=r"(prev) : "l"(&g_count) : "memory");
        if (prev == GRID - 1) {
            float total;
            asm volatile("atom.acquire.gpu.add.f32 %0, [%1], 0f00000000;"
                         : "=f"(total) : "l"(&g_acc) : "memory");
            out[0]  = total * (1.0f / (float)BATCH);
            g_acc   = 0.0f;
            g_count = 0u;
        }
    }
}

extern "C" void kernel_launch(void* const* d_in, const int* in_sizes, int n_in,
                              void* d_out, int out_size)
{
    const int*   context_words = (const int*)d_in[0];
    const int*   paths         = (const int*)d_in[1];
    const int*   codes         = (const int*)d_in[2];
    const int*   mask          = (const int*)d_in[3];
    const float* W_in          = (const float*)d_in[4];
    const float* W_internal    = (const float*)d_in[5];
    float*       out           = (float*)d_out;

    cbow_hs_kernel<<<GRID, THREADS>>>(context_words, paths, codes, mask,
                                      W_in, W_internal, out);
}

// round 15
// speedup vs baseline: 1.5804x; 1.5804x over previous
#include <cuda_runtime.h>

#define BATCH 16384
#define CTX   10
#define MAXC  24
#define EMBED 128
#define WPB   8
#define THREADS (WPB * 32)
#define GRID  ((BATCH + WPB - 1) / WPB)   // 2048
#define PITCH 36   // STS banks (4l+i)%32 distinct; 144B rows, 16B-aligned, LDS.128 conflict-free

// Grid-reduction state (validated R11): zero-init at module load; last block
// resets after publishing -> clean {0,0} every launch/replay. No fences
// (ordering rides on release/acquire atomics at L2), no allocation.
__device__ float        g_acc;
__device__ unsigned int g_count;

// Predicated vector gather: @p LDG.E.128, no branch; e stays 0 when pred==0.
__device__ __forceinline__ float4 pred_ldg128(const float4* addr, int pred) {
    float4 e = make_float4(0.f, 0.f, 0.f, 0.f);
    asm("{\n\t"
        ".reg .pred p;\n\t"
        "setp.ne.s32 p, %4, 0;\n\t"
        "@p ld.global.nc.v4.f32 {%0,%1,%2,%3}, [%5];\n\t"
        "}"
        : "+f"(e.x), "+f"(e.y), "+f"(e.z), "+f"(e.w)
        : "r"(pred), "l"(addr));
    return e;
}

// Issue one batch of 8 predicated node gathers (indices via warp-uniform
// int4 __ldg — never shuffles on the address path, per R9).
__device__ __forceinline__ void issue_batch(float4 E[8],
                                            const int4* p4, const int4* m4,
                                            int h, const float* W_internal,
                                            int lane) {
    const int4 P0 = __ldg(p4 + h * 2), P1 = __ldg(p4 + h * 2 + 1);
    const int4 M0 = __ldg(m4 + h * 2), M1 = __ldg(m4 + h * 2 + 1);
    const int nodes[8] = {P0.x, P0.y, P0.z, P0.w, P1.x, P1.y, P1.z, P1.w};
    const int mks[8]   = {M0.x, M0.y, M0.z, M0.w, M1.x, M1.y, M1.z, M1.w};
    #pragma unroll
    for (int k = 0; k < 8; k++)
        E[k] = pred_ldg128(reinterpret_cast<const float4*>(
                               W_internal + (long)nodes[k] * EMBED) + lane,
                           mks[k]);
}

__device__ __forceinline__ void consume_batch(const float4 E[8], float4 v,
                                              float* ws, int h, int lane) {
    #pragma unroll
    for (int k = 0; k < 8; k++) {
        const float pt = fmaf(v.x, E[k].x,
                         fmaf(v.y, E[k].y,
                         fmaf(v.z, E[k].z, v.w * E[k].w)));
        ws[(h * 8 + k) * PITCH + lane] = pt;   // conflict-free STS
    }
}

__global__ __launch_bounds__(THREADS, 5)   // 51-reg cap: room for the prefetched batch (R8 optimum)
void cbow_hs_kernel(const int* __restrict__ context_words,
                    const int* __restrict__ paths,
                    const int* __restrict__ codes,
                    const int* __restrict__ mask,     // int32 0/1
                    const float* __restrict__ W_in,
                    const float* __restrict__ W_internal,
                    float* __restrict__ out)
{
    const int warp_id = threadIdx.x >> 5;
    const int lane    = threadIdx.x & 31;
    const int row     = blockIdx.x * WPB + warp_id;

    __shared__ float wsum[WPB][MAXC * PITCH];   // 27.6 KB
    __shared__ float warp_loss[WPB];

    float contrib = 0.0f;

    if (row < BATCH) {
        float* ws = wsum[warp_id];
        const int4* p4 = reinterpret_cast<const int4*>(paths + row * MAXC);
        const int4* m4 = reinterpret_cast<const int4*>(mask  + row * MAXC);

        // ---- Entry: per-lane code/mask (kills the phase-3 tail round trip
        // — validated R9/R11). Overlaps the prefetch index loads below.
        const int li  = (lane < MAXC) ? lane : (MAXC - 1);
        const int cj  = __ldg(codes + row * MAXC + li);
        const int mlj = __ldg(mask  + row * MAXC + li);

        // ---- Software pipeline (R8, measured best): node batch 0 issued
        // FIRST; its round trip hides behind the context gathers.
        float4 E[8];
        issue_batch(E, p4, m4, 0, W_internal, lane);

        // ---- Phase 1: context vector (mean of 10 gathered 512B rows).
        const int* cw = context_words + row * CTX;
        float4 v = make_float4(0.f, 0.f, 0.f, 0.f);
        #pragma unroll
        for (int i = 0; i < CTX; i++) {
            const int w = __ldg(cw + i);
            const float4 e = __ldg(reinterpret_cast<const float4*>(
                                       W_in + (long)w * EMBED) + lane);
            v.x += e.x; v.y += e.y; v.z += e.z; v.w += e.w;
        }
        const float inv_ctx = 1.0f / (float)CTX;
        v.x *= inv_ctx; v.y *= inv_ctx; v.z *= inv_ctx; v.w *= inv_ctx;

        // ---- Phase 2: consume batch 0 (already arrived), then 1, 2.
        consume_batch(E, v, ws, 0, lane);
        issue_batch(E, p4, m4, 1, W_internal, lane);
        consume_batch(E, v, ws, 1, lane);
        issue_batch(E, p4, m4, 2, W_internal, lane);
        consume_batch(E, v, ws, 2, lane);
        __syncwarp();

        // ---- Phase 3: lane j (<24) sums step j's 32 partials via 8x LDS.128.
        // Zero global loads on the tail (cj/mlj resident since entry).
        if (lane < MAXC) {
            const float4* rp = reinterpret_cast<const float4*>(ws + lane * PITCH);
            float4 a0 = rp[0], a1 = rp[1], a2 = rp[2], a3 = rp[3];
            const float4 b0 = rp[4], b1 = rp[5], b2 = rp[6], b3 = rp[7];
            a0.x += b0.x; a0.y += b0.y; a0.z += b0.z; a0.w += b0.w;
            a1.x += b1.x; a1.y += b1.y; a1.z += b1.z; a1.w += b1.w;
            a2.x += b2.x; a2.y += b2.y; a2.z += b2.z; a2.w += b2.w;
            a3.x += b3.x; a3.y += b3.y; a3.z += b3.z; a3.w += b3.w;
            float s = ((a0.x + a0.y) + (a0.z + a0.w))
                    + ((a1.x + a1.y) + (a1.z + a1.w))
                    + ((a2.x + a2.y) + (a2.z + a2.w))
                    + ((a3.x + a3.y) + (a3.z + a3.w));

            const float sign = (float)(2 * cj - 1);
            const float x = -sign * s;
            // softplus(x) = max(x,0) + log(1 + exp(-|x|)), MUFU fast path
            const float sp = fmaxf(x, 0.0f) + __logf(1.0f + __expf(-fabsf(x)));
            contrib = mlj ? sp : 0.0f;
        }
    }

    // ---- Warp + block reduce (R4 measured optimum).
    contrib += __shfl_xor_sync(0xffffffffu, contrib, 16);
    contrib += __shfl_xor_sync(0xffffffffu, contrib, 8);
    contrib += __shfl_xor_sync(0xffffffffu, contrib, 4);
    contrib += __shfl_xor_sync(0xffffffffu, contrib, 2);
    contrib += __shfl_xor_sync(0xffffffffu, contrib, 1);

    if (lane == 0) warp_loss[warp_id] = contrib;
    __syncthreads();

    // ---- Fence-free grid finish (validated R11): release/acquire atomics,
    // no CCTL.IVALL, single graph node.
    if (threadIdx.x == 0) {
        float s = 0.0f;
        #pragma unroll
        for (int i = 0; i < WPB; i++) s += warp_loss[i];
        atomicAdd(&g_acc, s);                       // relaxed, L2-coherent

        unsigned int prev;
        asm volatile("atom.release.gpu.add.u32 %0, [%1], 1;"
                     : "=r"(prev) : "l"(&g_count) : "memory");
        if (prev == GRID - 1) {                     // last block: publish + reset
            float total;
            asm volatile("atom.acquire.gpu.add.f32 %0, [%1], 0f00000000;"
                         : "=f"(total) : "l"(&g_acc) : "memory");
            out[0]  = total * (1.0f / (float)BATCH);
            g_acc   = 0.0f;                         // launch boundary orders resets
            g_count = 0u;
        }
    }
}

extern "C" void kernel_launch(void* const* d_in, const int* in_sizes, int n_in,
                              void* d_out, int out_size)
{
    const int*   context_words = (const int*)d_in[0];
    const int*   paths         = (const int*)d_in[1];
    const int*   codes         = (const int*)d_in[2];
    const int*   mask          = (const int*)d_in[3];
    const float* W_in          = (const float*)d_in[4];
    const float* W_internal    = (const float*)d_in[5];
    float*       out           = (float*)d_out;

    cbow_hs_kernel<<<GRID, THREADS>>>(context_words, paths, codes, mask,
                                      W_in, W_internal, out);
}